// round 10
// baseline (speedup 1.0000x reference)
#include <cuda_runtime.h>
#include <cuda_bf16.h>

#define NNODES 100000
#define NEDGES 1600000
#define INDIM  1433
#define HID    50
#define OUTD   7
#define KCHUNKS 45     // ceil(1433/32)

// ---------------- scratch (static device memory; zero-initialized at load) ----
__device__ int   g_counts[NNODES];        // re-zeroed by scan_add for next replay
__device__ int   g_rowptr[NNODES + 1];
__device__ int   g_cursor[NNODES];
__device__ int   g_bsums[128];
__device__ int2  g_edge[NEDGES];          // {src, bits(dinv[src])}
__device__ float g_dinv[NNODES];
__device__ __nv_bfloat16 g_h1b[NNODES * 64];  // layer-1 linear out, bf16 (pad cols stay 0)
__device__ float g_z[NNODES * 8];             // layer-2 linear out (col 7 stays 0)
__device__ float g_w1p[KCHUNKS * 2048];       // W1 pre-padded: [45][32][64]

// ---------------- ptx helpers ----------------
__device__ __forceinline__ void mma_tf32(float* c,
                                         unsigned a0, unsigned a1, unsigned a2, unsigned a3,
                                         unsigned b0, unsigned b1) {
    asm("mma.sync.aligned.m16n8k8.row.col.f32.tf32.tf32.f32 "
        "{%0,%1,%2,%3}, {%4,%5,%6,%7}, {%8,%9}, {%0,%1,%2,%3};"
        : "+f"(c[0]), "+f"(c[1]), "+f"(c[2]), "+f"(c[3])
        : "r"(a0), "r"(a1), "r"(a2), "r"(a3), "r"(b0), "r"(b1));
}

// ---------------- W1 pre-pad: [45][32][64], zero padding ----------------
__global__ void w1pad_kernel(const float* __restrict__ w1) {
    int i = blockIdx.x * 256 + threadIdx.x;
    if (i < KCHUNKS * 2048) {
        int kc = i >> 11, rem = i & 2047;
        int kk = rem >> 6, n = rem & 63;
        int k = kc * 32 + kk;
        g_w1p[i] = (k < INDIM && n < HID) ? __ldg(&w1[k * HID + n]) : 0.f;
    }
}

// ---------------- CSR build ----------------
__global__ void count_kernel(const int* __restrict__ col) {
    int i = blockIdx.x * blockDim.x + threadIdx.x;
    if (i < NEDGES) atomicAdd(&g_counts[__ldg(&col[i])], 1);
}

// local scan of counts + dinv computation (fused)
__global__ void scan_local_kernel() {
    __shared__ int ws[32];
    int tid = threadIdx.x;
    int i = blockIdx.x * 1024 + tid;
    int v = (i < NNODES) ? g_counts[i] : 0;
    if (i < NNODES) g_dinv[i] = rsqrtf((float)(v + 1));  // +1 self loop
    int x = v;
#pragma unroll
    for (int d = 1; d < 32; d <<= 1) {
        int y = __shfl_up_sync(0xffffffffu, x, d);
        if ((tid & 31) >= d) x += y;
    }
    if ((tid & 31) == 31) ws[tid >> 5] = x;
    __syncthreads();
    if (tid < 32) {
        int w = ws[tid];
#pragma unroll
        for (int d = 1; d < 32; d <<= 1) {
            int y = __shfl_up_sync(0xffffffffu, w, d);
            if (tid >= d) w += y;
        }
        ws[tid] = w;
    }
    __syncthreads();
    int woff = (tid >= 32) ? ws[(tid >> 5) - 1] : 0;
    int incl = x + woff;
    if (i < NNODES) g_rowptr[i] = incl - v;       // local exclusive
    if (tid == 1023) g_bsums[blockIdx.x] = incl;  // block total
}

__global__ void scan_bsums_kernel() {
    __shared__ int ws[4];
    int tid = threadIdx.x;
    int v = (tid < 98) ? g_bsums[tid] : 0;
    int x = v;
#pragma unroll
    for (int d = 1; d < 32; d <<= 1) {
        int y = __shfl_up_sync(0xffffffffu, x, d);
        if ((tid & 31) >= d) x += y;
    }
    if ((tid & 31) == 31) ws[tid >> 5] = x;
    __syncthreads();
    if (tid < 4) {
        int wv = ws[tid];
#pragma unroll
        for (int d = 1; d < 4; d <<= 1) {
            int y = __shfl_up_sync(0x0000000fu, wv, d);
            if (tid >= d) wv += y;
        }
        ws[tid] = wv;
    }
    __syncthreads();
    int off = (tid >= 32) ? ws[(tid >> 5) - 1] : 0;
    if (tid < 98) g_bsums[tid] = x + off - v;
}

__global__ void scan_add_kernel() {
    int i = blockIdx.x * blockDim.x + threadIdx.x;
    if (i < NNODES) {
        int val = g_rowptr[i] + g_bsums[i >> 10];
        g_rowptr[i] = val;
        g_cursor[i] = val;
        g_counts[i] = 0;  // reset for next graph replay
    }
    if (i == 0) g_rowptr[NNODES] = NEDGES;
}

__global__ void scatter_kernel(const int* __restrict__ row, const int* __restrict__ col) {
    int i = blockIdx.x * blockDim.x + threadIdx.x;
    if (i < NEDGES) {
        int c = __ldg(&col[i]);
        int r = __ldg(&row[i]);
        int p = atomicAdd(&g_cursor[c], 1);
        g_edge[p] = make_int2(r, __float_as_int(__ldg(&g_dinv[r])));
    }
}

// ---------------- GEMM1: h1 = x @ W1 (tf32 HMMA, fully barrier-free) ---------
// BOTH A and B fragments loaded directly from gmem into MMA fragments:
// no smem, no cp.async, no __syncthreads — warps are independent streams of
// LDG + HMMA, latency covered by 16 free-running warps/SM.
// Per chunk per thread: 32 A loads (32B-sector perfect) + 56 B loads
// (4×32B sectors per warp-load, 100% utilization, L1/L2-resident g_w1p).
// 128 threads = 4 warps; block tile M=128 (warp 32 rows), N=56, K chunk 32.
__global__ __launch_bounds__(128, 4) void gemm1_kernel(const float* __restrict__ x) {
    int t = threadIdx.x, lane = t & 31, w = t >> 5;
    int gid = lane >> 2, tg = lane & 3;
    int mbase = blockIdx.x * 128;
    int rw = mbase + w * 32;

    float acc[14][4];  // [mt*7+nt][j]
#pragma unroll
    for (int i = 0; i < 14; i++)
#pragma unroll
        for (int j = 0; j < 4; j++) acc[i][j] = 0.f;

    // per-thread A row pointers + validity (rows: rw + mt*16 + gid, +8)
    const float* xp[4];
    bool rok[4];
#pragma unroll
    for (int mt = 0; mt < 2; mt++) {
        int r0 = rw + mt * 16 + gid;
        int r1 = r0 + 8;
        rok[mt * 2]     = r0 < NNODES;
        rok[mt * 2 + 1] = r1 < NNODES;
        xp[mt * 2]      = x + (size_t)(rok[mt * 2] ? r0 : 0) * INDIM;
        xp[mt * 2 + 1]  = x + (size_t)(rok[mt * 2 + 1] ? r1 : 0) * INDIM;
    }

    // B fragment base: lane reads g_w1p[kc][kk + tg (+4)][nt*8 + gid]
    const float* bp = g_w1p + gid;

    for (int kc = 0; kc < KCHUNKS; kc++) {
        int kb = kc * 32;

        // A fragments for this chunk (issued first; latency overlapped with
        // the B loads + MMAs below and across free-running warps)
        float aF[2][4][4];  // [mt][k8][j]
#pragma unroll
        for (int k8 = 0; k8 < 4; k8++) {
            int c0 = kb + k8 * 8 + tg;
            bool c0ok = c0 < INDIM;
            bool c1ok = (c0 + 4) < INDIM;
#pragma unroll
            for (int mt = 0; mt < 2; mt++) {
                aF[mt][k8][0] = (rok[mt * 2]     && c0ok) ? __ldg(xp[mt * 2] + c0)         : 0.f;
                aF[mt][k8][1] = (rok[mt * 2 + 1] && c0ok) ? __ldg(xp[mt * 2 + 1] + c0)     : 0.f;
                aF[mt][k8][2] = (rok[mt * 2]     && c1ok) ? __ldg(xp[mt * 2] + c0 + 4)     : 0.f;
                aF[mt][k8][3] = (rok[mt * 2 + 1] && c1ok) ? __ldg(xp[mt * 2 + 1] + c0 + 4) : 0.f;
            }
        }

        const float* bc = bp + kc * 2048;  // [kc][0][gid]
#pragma unroll
        for (int k8 = 0; k8 < 4; k8++) {
            int kk = k8 * 8;
            unsigned b0[7], b1[7];
#pragma unroll
            for (int nt = 0; nt < 7; nt++) {
                b0[nt] = __float_as_uint(__ldg(bc + (kk + tg) * 64 + nt * 8));
                b1[nt] = __float_as_uint(__ldg(bc + (kk + tg + 4) * 64 + nt * 8));
            }
#pragma unroll
            for (int mt = 0; mt < 2; mt++) {
#pragma unroll
                for (int nt = 0; nt < 7; nt++)
                    mma_tf32(acc[mt * 7 + nt],
                             __float_as_uint(aF[mt][k8][0]), __float_as_uint(aF[mt][k8][1]),
                             __float_as_uint(aF[mt][k8][2]), __float_as_uint(aF[mt][k8][3]),
                             b0[nt], b1[nt]);
            }
        }
    }

    // epilogue: write bf16 pairs (c0 in {0,2,..,48})
    unsigned* hout = (unsigned*)g_h1b;
#pragma unroll
    for (int mt = 0; mt < 2; mt++) {
#pragma unroll
        for (int nt = 0; nt < 7; nt++) {
            int c0 = nt * 8 + tg * 2;
            if (c0 < HID) {
#pragma unroll
                for (int h = 0; h < 2; h++) {
                    int r = mbase + w * 32 + mt * 16 + gid + h * 8;
                    if (r < NNODES) {
                        __nv_bfloat162 bv = __float22bfloat162_rn(
                            make_float2(acc[mt * 7 + nt][h * 2], acc[mt * 7 + nt][h * 2 + 1]));
                        hout[(size_t)r * 32 + (c0 >> 1)] = *(unsigned*)&bv;
                    }
                }
            }
        }
    }
}

// ---------------- Aggregation 1 + fused lin2 (R6 champion form) --------------
// 1 node per warp; lane covers cols {2*lane, 2*lane+1} as one bf16x2 word.
__global__ __launch_bounds__(256) void agg1_kernel(const float* __restrict__ b1,
                                                   const float* __restrict__ w2) {
    __shared__ float w2s[HID * OUTD];
    int t = threadIdx.x, lane = t & 31, w = t >> 5;
    for (int i = t; i < HID * OUTD; i += 256) w2s[i] = __ldg(&w2[i]);
    __syncthreads();
    int v = blockIdx.x * 8 + w;
    if (v >= NNODES) return;
    int s0 = __ldg(&g_rowptr[v]);
    int s1 = __ldg(&g_rowptr[v + 1]);
    float dv = __ldg(&g_dinv[v]);
    const unsigned* hb = (const unsigned*)g_h1b;

    unsigned su = __ldg(&hb[(size_t)v * 32 + lane]);
    float2 self = __bfloat1622float2(*(__nv_bfloat162*)&su);
    float ax = dv * self.x, ay = dv * self.y;
    int j = s0;
    for (; j + 3 < s1; j += 4) {
        int2 e0 = __ldg(&g_edge[j]);
        int2 e1 = __ldg(&g_edge[j + 1]);
        int2 e2 = __ldg(&g_edge[j + 2]);
        int2 e3 = __ldg(&g_edge[j + 3]);
        unsigned u0 = __ldg(&hb[(size_t)e0.x * 32 + lane]);
        unsigned u1 = __ldg(&hb[(size_t)e1.x * 32 + lane]);
        unsigned u2 = __ldg(&hb[(size_t)e2.x * 32 + lane]);
        unsigned u3 = __ldg(&hb[(size_t)e3.x * 32 + lane]);
        float2 h0 = __bfloat1622float2(*(__nv_bfloat162*)&u0);
        float2 h1v = __bfloat1622float2(*(__nv_bfloat162*)&u1);
        float2 h2 = __bfloat1622float2(*(__nv_bfloat162*)&u2);
        float2 h3 = __bfloat1622float2(*(__nv_bfloat162*)&u3);
        float w0 = __int_as_float(e0.y), w1v = __int_as_float(e1.y);
        float w2v = __int_as_float(e2.y), w3 = __int_as_float(e3.y);
        ax = fmaf(w0, h0.x, ax);   ay = fmaf(w0, h0.y, ay);
        ax = fmaf(w1v, h1v.x, ax); ay = fmaf(w1v, h1v.y, ay);
        ax = fmaf(w2v, h2.x, ax);  ay = fmaf(w2v, h2.y, ay);
        ax = fmaf(w3, h3.x, ax);   ay = fmaf(w3, h3.y, ay);
    }
    for (; j < s1; j++) {
        int2 e = __ldg(&g_edge[j]);
        unsigned u0 = __ldg(&hb[(size_t)e.x * 32 + lane]);
        float2 h0 = __bfloat1622float2(*(__nv_bfloat162*)&u0);
        float we = __int_as_float(e.y);
        ax = fmaf(we, h0.x, ax);
        ay = fmaf(we, h0.y, ay);
    }
    int f0 = 2 * lane, f1 = 2 * lane + 1;
    float o1x = (f0 < HID) ? fmaxf(fmaf(dv, ax, __ldg(&b1[f0])), 0.f) : 0.f;
    float o1y = (f1 < HID) ? fmaxf(fmaf(dv, ay, __ldg(&b1[f1])), 0.f) : 0.f;
    float z[7];
#pragma unroll
    for (int jo = 0; jo < 7; jo++) {
        float p = 0.f;
        if (f0 < HID) p = o1x * w2s[f0 * OUTD + jo];
        if (f1 < HID) p = fmaf(o1y, w2s[f1 * OUTD + jo], p);
#pragma unroll
        for (int d = 16; d >= 1; d >>= 1) p += __shfl_xor_sync(0xffffffffu, p, d);
        z[jo] = p;
    }
    if (lane == 0) {
#pragma unroll
        for (int jo = 0; jo < 7; jo++) g_z[(size_t)v * 8 + jo] = z[jo];
    }
}

// ---------------- Aggregation 2 (+b2, sigmoid; R6 champion form) -------------
__global__ __launch_bounds__(256) void agg2_kernel(const float* __restrict__ b2,
                                                   float* __restrict__ out) {
    int t = threadIdx.x;
    int jj = t & 7;
    int v = blockIdx.x * 32 + (t >> 3);
    int s0 = __ldg(&g_rowptr[v]);
    int s1 = __ldg(&g_rowptr[v + 1]);
    float dv = __ldg(&g_dinv[v]);
    float acc = dv * __ldg(&g_z[(size_t)v * 8 + jj]);
    int j = s0;
    for (; j + 3 < s1; j += 4) {
        int2 e0 = __ldg(&g_edge[j]);
        int2 e1 = __ldg(&g_edge[j + 1]);
        int2 e2 = __ldg(&g_edge[j + 2]);
        int2 e3 = __ldg(&g_edge[j + 3]);
        acc = fmaf(__int_as_float(e0.y), __ldg(&g_z[(size_t)e0.x * 8 + jj]), acc);
        acc = fmaf(__int_as_float(e1.y), __ldg(&g_z[(size_t)e1.x * 8 + jj]), acc);
        acc = fmaf(__int_as_float(e2.y), __ldg(&g_z[(size_t)e2.x * 8 + jj]), acc);
        acc = fmaf(__int_as_float(e3.y), __ldg(&g_z[(size_t)e3.x * 8 + jj]), acc);
    }
    for (; j < s1; j++) {
        int2 e = __ldg(&g_edge[j]);
        acc = fmaf(__int_as_float(e.y), __ldg(&g_z[(size_t)e.x * 8 + jj]), acc);
    }
    if (jj < OUTD) {
        float zz = fmaf(dv, acc, __ldg(&b2[jj]));
        out[v * OUTD + jj] = 1.f / (1.f + __expf(-zz));
    }
}

// ---------------- launch (two-stream fork/join for CSR || GEMM overlap) ------
struct AsyncRes {
    cudaStream_t s1;
    cudaEvent_t eFork, eJoin;
    AsyncRes() {
        cudaStreamCreateWithFlags(&s1, cudaStreamNonBlocking);
        cudaEventCreateWithFlags(&eFork, cudaEventDisableTiming);
        cudaEventCreateWithFlags(&eJoin, cudaEventDisableTiming);
    }
};

extern "C" void kernel_launch(void* const* d_in, const int* in_sizes, int n_in,
                              void* d_out, int out_size) {
    static AsyncRes ar;  // created on first (non-captured) correctness call

    const float* x  = (const float*)d_in[0];
    const int*   ei = (const int*)d_in[1];
    const float* w1 = (const float*)d_in[2];
    const float* b1 = (const float*)d_in[3];
    const float* w2 = (const float*)d_in[4];
    const float* b2 = (const float*)d_in[5];
    float* out = (float*)d_out;

    const int* row = ei;            // edge_index[0] = src
    const int* col = ei + NEDGES;   // edge_index[1] = dst

    // fork: CSR chain on s1, GEMM path on stream 0 — fully independent
    cudaEventRecord(ar.eFork, 0);
    cudaStreamWaitEvent(ar.s1, ar.eFork, 0);

    // stream 0: dense path
    w1pad_kernel<<<360, 256>>>(w1);
    gemm1_kernel<<<782, 128>>>(x);

    // stream s1: CSR build (hidden under gemm1)
    count_kernel<<<6250, 256, 0, ar.s1>>>(col);
    scan_local_kernel<<<98, 1024, 0, ar.s1>>>();      // also computes dinv
    scan_bsums_kernel<<<1, 128, 0, ar.s1>>>();
    scan_add_kernel<<<391, 256, 0, ar.s1>>>();        // also zeroes counts
    scatter_kernel<<<6250, 256, 0, ar.s1>>>(row, col);

    // join
    cudaEventRecord(ar.eJoin, ar.s1);
    cudaStreamWaitEvent(0, ar.eJoin, 0);

    // aggregations (need both paths)
    agg1_kernel<<<12500, 256>>>(b1, w2);              // fused lin2
    agg2_kernel<<<3125, 256>>>(b2, out);
}

// round 12
// speedup vs baseline: 1.3081x; 1.3081x over previous
#include <cuda_runtime.h>
#include <cuda_bf16.h>

#define NNODES 100000
#define NEDGES 1600000
#define INDIM  1433
#define HID    50
#define OUTD   7
#define KCHUNKS 45     // ceil(1433/32)

// ---------------- scratch (static device memory; zero-initialized at load) ----
__device__ int   g_counts[NNODES];        // re-zeroed by scan_add for next replay
__device__ int   g_rowptr[NNODES + 1];
__device__ int   g_cursor[NNODES];
__device__ int   g_bsums[128];
__device__ int2  g_edge[NEDGES];          // {src, bits(dinv[src])}
__device__ float g_dinv[NNODES];
__device__ __nv_bfloat16 g_h1b[NNODES * 64];  // layer-1 linear out, bf16 (pad cols stay 0)
__device__ float g_z[NNODES * 8];             // layer-2 linear out (col 7 stays 0)
__device__ float g_w1p[KCHUNKS * 2048];       // W1 pre-padded: [45][32][64]

// ---------------- ptx helpers ----------------
__device__ __forceinline__ void mma_tf32(float* c,
                                         unsigned a0, unsigned a1, unsigned a2, unsigned a3,
                                         unsigned b0, unsigned b1) {
    asm("mma.sync.aligned.m16n8k8.row.col.f32.tf32.tf32.f32 "
        "{%0,%1,%2,%3}, {%4,%5,%6,%7}, {%8,%9}, {%0,%1,%2,%3};"
        : "+f"(c[0]), "+f"(c[1]), "+f"(c[2]), "+f"(c[3])
        : "r"(a0), "r"(a1), "r"(a2), "r"(a3), "r"(b0), "r"(b1));
}

__device__ __forceinline__ void cp_async16(unsigned dst, const float4* src) {
    asm volatile("cp.async.cg.shared.global [%0], [%1], 16;" :: "r"(dst), "l"(src));
}
__device__ __forceinline__ void cp_commit() { asm volatile("cp.async.commit_group;"); }
__device__ __forceinline__ void cp_wait1() { asm volatile("cp.async.wait_group 1;"); }
__device__ __forceinline__ void cp_wait0() { asm volatile("cp.async.wait_group 0;"); }
__device__ __forceinline__ void prefetch_l2(const void* p) {
    asm volatile("prefetch.global.L2 [%0];" :: "l"(p));
}

// ---------------- W1 pre-pad: [45][32][64], zero padding ----------------
__global__ void w1pad_kernel(const float* __restrict__ w1) {
    int i = blockIdx.x * 256 + threadIdx.x;
    if (i < KCHUNKS * 2048) {
        int kc = i >> 11, rem = i & 2047;
        int kk = rem >> 6, n = rem & 63;
        int k = kc * 32 + kk;
        g_w1p[i] = (k < INDIM && n < HID) ? __ldg(&w1[k * HID + n]) : 0.f;
    }
}

// ---------------- CSR build ----------------
__global__ void count_kernel(const int* __restrict__ col) {
    int i = blockIdx.x * blockDim.x + threadIdx.x;
    if (i < NEDGES) atomicAdd(&g_counts[__ldg(&col[i])], 1);
}

// local scan of counts + dinv computation (fused)
__global__ void scan_local_kernel() {
    __shared__ int ws[32];
    int tid = threadIdx.x;
    int i = blockIdx.x * 1024 + tid;
    int v = (i < NNODES) ? g_counts[i] : 0;
    if (i < NNODES) g_dinv[i] = rsqrtf((float)(v + 1));  // +1 self loop
    int x = v;
#pragma unroll
    for (int d = 1; d < 32; d <<= 1) {
        int y = __shfl_up_sync(0xffffffffu, x, d);
        if ((tid & 31) >= d) x += y;
    }
    if ((tid & 31) == 31) ws[tid >> 5] = x;
    __syncthreads();
    if (tid < 32) {
        int w = ws[tid];
#pragma unroll
        for (int d = 1; d < 32; d <<= 1) {
            int y = __shfl_up_sync(0xffffffffu, w, d);
            if (tid >= d) w += y;
        }
        ws[tid] = w;
    }
    __syncthreads();
    int woff = (tid >= 32) ? ws[(tid >> 5) - 1] : 0;
    int incl = x + woff;
    if (i < NNODES) g_rowptr[i] = incl - v;       // local exclusive
    if (tid == 1023) g_bsums[blockIdx.x] = incl;  // block total
}

__global__ void scan_bsums_kernel() {
    __shared__ int ws[4];
    int tid = threadIdx.x;
    int v = (tid < 98) ? g_bsums[tid] : 0;
    int x = v;
#pragma unroll
    for (int d = 1; d < 32; d <<= 1) {
        int y = __shfl_up_sync(0xffffffffu, x, d);
        if ((tid & 31) >= d) x += y;
    }
    if ((tid & 31) == 31) ws[tid >> 5] = x;
    __syncthreads();
    if (tid < 4) {
        int wv = ws[tid];
#pragma unroll
        for (int d = 1; d < 4; d <<= 1) {
            int y = __shfl_up_sync(0x0000000fu, wv, d);
            if (tid >= d) wv += y;
        }
        ws[tid] = wv;
    }
    __syncthreads();
    int off = (tid >= 32) ? ws[(tid >> 5) - 1] : 0;
    if (tid < 98) g_bsums[tid] = x + off - v;
}

__global__ void scan_add_kernel() {
    int i = blockIdx.x * blockDim.x + threadIdx.x;
    if (i < NNODES) {
        int val = g_rowptr[i] + g_bsums[i >> 10];
        g_rowptr[i] = val;
        g_cursor[i] = val;
        g_counts[i] = 0;  // reset for next graph replay
    }
    if (i == 0) g_rowptr[NNODES] = NEDGES;
}

__global__ void scatter_kernel(const int* __restrict__ row, const int* __restrict__ col) {
    int i = blockIdx.x * blockDim.x + threadIdx.x;
    if (i < NEDGES) {
        int c = __ldg(&col[i]);
        int r = __ldg(&row[i]);
        int p = atomicAdd(&g_cursor[c], 1);
        g_edge[p] = make_int2(r, __float_as_int(__ldg(&g_dinv[r])));
    }
}

// ---------------- GEMM1: h1 = x @ W1 (tf32 HMMA) — R4 champion + L2 prefetch -
// A fragments loaded DIRECTLY from gmem (no smem roundtrip); next chunk's A
// lines prefetched into L2 (no register writes -> no scoreboard coupling).
// B double-buffered in smem via cp.async 16B (from padded g_w1p).
// 128 threads = 4 warps; block tile M=128 (warp 32 rows), N=56, K chunk 32.
#define BLD 72   // Bs ld: frag bank = (8*tg+gid) mod 32 -> conflict-free

__global__ __launch_bounds__(128, 4) void gemm1_kernel(const float* __restrict__ x) {
    __shared__ float Bs[2][32 * BLD];
    int t = threadIdx.x, lane = t & 31, w = t >> 5;
    int gid = lane >> 2, tg = lane & 3;
    int mbase = blockIdx.x * 128;
    int rw = mbase + w * 32;

    unsigned bsb = (unsigned)__cvta_generic_to_shared(&Bs[0][0]);
    const float4* w1p4 = (const float4*)g_w1p;

    float acc[14][4];  // [mt*7+nt][j]
#pragma unroll
    for (int i = 0; i < 14; i++)
#pragma unroll
        for (int j = 0; j < 4; j++) acc[i][j] = 0.f;

    // per-thread A row pointers + validity (rows: rw + mt*16 + gid, +8)
    const float* xp[4];
    bool rok[4];
#pragma unroll
    for (int mt = 0; mt < 2; mt++) {
        int r0 = rw + mt * 16 + gid;
        int r1 = r0 + 8;
        rok[mt * 2]     = r0 < NNODES;
        rok[mt * 2 + 1] = r1 < NNODES;
        xp[mt * 2]      = x + (size_t)(rok[mt * 2] ? r0 : 0) * INDIM;
        xp[mt * 2 + 1]  = x + (size_t)(rok[mt * 2 + 1] ? r1 : 0) * INDIM;
    }

    auto stageB = [&](int kc, int buf) {
        unsigned bbase = bsb + buf * (32 * BLD * 4);
#pragma unroll
        for (int i = 0; i < 4; i++) {
            int idx = (t + i * 128) * 4;          // float index in [0,2048)
            int kk = idx >> 6, n = idx & 63;
            cp_async16(bbase + (kk * BLD + n) * 4, &w1p4[kc * 512 + t + i * 128]);
        }
        cp_commit();
    };

    stageB(0, 0);

    for (int kc = 0; kc < KCHUNKS; kc++) {
        int buf = kc & 1;
        int kb = kc * 32;

        // A fragments for this chunk: direct LDG (issued early, latency hidden
        // under B wait + sync + LDS below, and by desynchronized sibling CTAs)
        float aF[2][4][4];  // [mt][k8][j]
#pragma unroll
        for (int k8 = 0; k8 < 4; k8++) {
            int c0 = kb + k8 * 8 + tg;
            bool c0ok = c0 < INDIM;
            bool c1ok = (c0 + 4) < INDIM;
#pragma unroll
            for (int mt = 0; mt < 2; mt++) {
                aF[mt][k8][0] = (rok[mt * 2]     && c0ok) ? __ldg(xp[mt * 2] + c0)         : 0.f;
                aF[mt][k8][1] = (rok[mt * 2 + 1] && c0ok) ? __ldg(xp[mt * 2 + 1] + c0)     : 0.f;
                aF[mt][k8][2] = (rok[mt * 2]     && c1ok) ? __ldg(xp[mt * 2] + c0 + 4)     : 0.f;
                aF[mt][k8][3] = (rok[mt * 2 + 1] && c1ok) ? __ldg(xp[mt * 2 + 1] + c0 + 4) : 0.f;
            }
        }

        // L2-prefetch next chunk's A lines. Rows are shared across the 4 lanes
        // of a quad -> only tg==0 lanes issue (predicated-off lanes are free).
        // 128B span may straddle 2 lines (row stride 5732B % 128 != 0).
        if (kc + 1 < KCHUNKS && tg == 0) {
            int nb = kb + 32;
            if (nb + 31 < INDIM + 31) {  // always true; keeps compiler from hoisting oddly
#pragma unroll
                for (int q = 0; q < 4; q++) {
                    if (rok[q]) {
                        const char* p = (const char*)(xp[q] + nb);
                        prefetch_l2(p);
                        prefetch_l2(p + 124);
                    }
                }
            }
        }

        if (kc + 1 < KCHUNKS) { stageB(kc + 1, buf ^ 1); cp_wait1(); }
        else cp_wait0();
        __syncthreads();

        const float* B = &Bs[buf][0];
#pragma unroll
        for (int k8 = 0; k8 < 4; k8++) {
            int kk = k8 * 8;
            unsigned b0[7], b1[7];
#pragma unroll
            for (int nt = 0; nt < 7; nt++) {
                b0[nt] = __float_as_uint(B[(kk + tg) * BLD + nt * 8 + gid]);
                b1[nt] = __float_as_uint(B[(kk + tg + 4) * BLD + nt * 8 + gid]);
            }
#pragma unroll
            for (int mt = 0; mt < 2; mt++) {
#pragma unroll
                for (int nt = 0; nt < 7; nt++)
                    mma_tf32(acc[mt * 7 + nt],
                             __float_as_uint(aF[mt][k8][0]), __float_as_uint(aF[mt][k8][1]),
                             __float_as_uint(aF[mt][k8][2]), __float_as_uint(aF[mt][k8][3]),
                             b0[nt], b1[nt]);
            }
        }
        __syncthreads();  // Bs[buf] free before restage in next iteration
    }

    // epilogue: write bf16 pairs (c0 in {0,2,..,48})
    unsigned* hout = (unsigned*)g_h1b;
#pragma unroll
    for (int mt = 0; mt < 2; mt++) {
#pragma unroll
        for (int nt = 0; nt < 7; nt++) {
            int c0 = nt * 8 + tg * 2;
            if (c0 < HID) {
#pragma unroll
                for (int h = 0; h < 2; h++) {
                    int r = mbase + w * 32 + mt * 16 + gid + h * 8;
                    if (r < NNODES) {
                        __nv_bfloat162 bv = __float22bfloat162_rn(
                            make_float2(acc[mt * 7 + nt][h * 2], acc[mt * 7 + nt][h * 2 + 1]));
                        hout[(size_t)r * 32 + (c0 >> 1)] = *(unsigned*)&bv;
                    }
                }
            }
        }
    }
}

// ---------------- Aggregation 1 + fused lin2 (R6 champion form) --------------
// 1 node per warp; lane covers cols {2*lane, 2*lane+1} as one bf16x2 word.
__global__ __launch_bounds__(256) void agg1_kernel(const float* __restrict__ b1,
                                                   const float* __restrict__ w2) {
    __shared__ float w2s[HID * OUTD];
    int t = threadIdx.x, lane = t & 31, w = t >> 5;
    for (int i = t; i < HID * OUTD; i += 256) w2s[i] = __ldg(&w2[i]);
    __syncthreads();
    int v = blockIdx.x * 8 + w;
    if (v >= NNODES) return;
    int s0 = __ldg(&g_rowptr[v]);
    int s1 = __ldg(&g_rowptr[v + 1]);
    float dv = __ldg(&g_dinv[v]);
    const unsigned* hb = (const unsigned*)g_h1b;

    unsigned su = __ldg(&hb[(size_t)v * 32 + lane]);
    float2 self = __bfloat1622float2(*(__nv_bfloat162*)&su);
    float ax = dv * self.x, ay = dv * self.y;
    int j = s0;
    for (; j + 3 < s1; j += 4) {
        int2 e0 = __ldg(&g_edge[j]);
        int2 e1 = __ldg(&g_edge[j + 1]);
        int2 e2 = __ldg(&g_edge[j + 2]);
        int2 e3 = __ldg(&g_edge[j + 3]);
        unsigned u0 = __ldg(&hb[(size_t)e0.x * 32 + lane]);
        unsigned u1 = __ldg(&hb[(size_t)e1.x * 32 + lane]);
        unsigned u2 = __ldg(&hb[(size_t)e2.x * 32 + lane]);
        unsigned u3 = __ldg(&hb[(size_t)e3.x * 32 + lane]);
        float2 h0 = __bfloat1622float2(*(__nv_bfloat162*)&u0);
        float2 h1v = __bfloat1622float2(*(__nv_bfloat162*)&u1);
        float2 h2 = __bfloat1622float2(*(__nv_bfloat162*)&u2);
        float2 h3 = __bfloat1622float2(*(__nv_bfloat162*)&u3);
        float w0 = __int_as_float(e0.y), w1v = __int_as_float(e1.y);
        float w2v = __int_as_float(e2.y), w3 = __int_as_float(e3.y);
        ax = fmaf(w0, h0.x, ax);   ay = fmaf(w0, h0.y, ay);
        ax = fmaf(w1v, h1v.x, ax); ay = fmaf(w1v, h1v.y, ay);
        ax = fmaf(w2v, h2.x, ax);  ay = fmaf(w2v, h2.y, ay);
        ax = fmaf(w3, h3.x, ax);   ay = fmaf(w3, h3.y, ay);
    }
    for (; j < s1; j++) {
        int2 e = __ldg(&g_edge[j]);
        unsigned u0 = __ldg(&hb[(size_t)e.x * 32 + lane]);
        float2 h0 = __bfloat1622float2(*(__nv_bfloat162*)&u0);
        float we = __int_as_float(e.y);
        ax = fmaf(we, h0.x, ax);
        ay = fmaf(we, h0.y, ay);
    }
    int f0 = 2 * lane, f1 = 2 * lane + 1;
    float o1x = (f0 < HID) ? fmaxf(fmaf(dv, ax, __ldg(&b1[f0])), 0.f) : 0.f;
    float o1y = (f1 < HID) ? fmaxf(fmaf(dv, ay, __ldg(&b1[f1])), 0.f) : 0.f;
    float z[7];
#pragma unroll
    for (int jo = 0; jo < 7; jo++) {
        float p = 0.f;
        if (f0 < HID) p = o1x * w2s[f0 * OUTD + jo];
        if (f1 < HID) p = fmaf(o1y, w2s[f1 * OUTD + jo], p);
#pragma unroll
        for (int d = 16; d >= 1; d >>= 1) p += __shfl_xor_sync(0xffffffffu, p, d);
        z[jo] = p;
    }
    if (lane == 0) {
#pragma unroll
        for (int jo = 0; jo < 7; jo++) g_z[(size_t)v * 8 + jo] = z[jo];
    }
}

// ---------------- Aggregation 2 (+b2, sigmoid; R6 champion form) -------------
__global__ __launch_bounds__(256) void agg2_kernel(const float* __restrict__ b2,
                                                   float* __restrict__ out) {
    int t = threadIdx.x;
    int jj = t & 7;
    int v = blockIdx.x * 32 + (t >> 3);
    int s0 = __ldg(&g_rowptr[v]);
    int s1 = __ldg(&g_rowptr[v + 1]);
    float dv = __ldg(&g_dinv[v]);
    float acc = dv * __ldg(&g_z[(size_t)v * 8 + jj]);
    int j = s0;
    for (; j + 3 < s1; j += 4) {
        int2 e0 = __ldg(&g_edge[j]);
        int2 e1 = __ldg(&g_edge[j + 1]);
        int2 e2 = __ldg(&g_edge[j + 2]);
        int2 e3 = __ldg(&g_edge[j + 3]);
        acc = fmaf(__int_as_float(e0.y), __ldg(&g_z[(size_t)e0.x * 8 + jj]), acc);
        acc = fmaf(__int_as_float(e1.y), __ldg(&g_z[(size_t)e1.x * 8 + jj]), acc);
        acc = fmaf(__int_as_float(e2.y), __ldg(&g_z[(size_t)e2.x * 8 + jj]), acc);
        acc = fmaf(__int_as_float(e3.y), __ldg(&g_z[(size_t)e3.x * 8 + jj]), acc);
    }
    for (; j < s1; j++) {
        int2 e = __ldg(&g_edge[j]);
        acc = fmaf(__int_as_float(e.y), __ldg(&g_z[(size_t)e.x * 8 + jj]), acc);
    }
    if (jj < OUTD) {
        float zz = fmaf(dv, acc, __ldg(&b2[jj]));
        out[v * OUTD + jj] = 1.f / (1.f + __expf(-zz));
    }
}

// ---------------- launch (two-stream fork/join for CSR || GEMM overlap) ------
struct AsyncRes {
    cudaStream_t s1;
    cudaEvent_t eFork, eJoin;
    AsyncRes() {
        cudaStreamCreateWithFlags(&s1, cudaStreamNonBlocking);
        cudaEventCreateWithFlags(&eFork, cudaEventDisableTiming);
        cudaEventCreateWithFlags(&eJoin, cudaEventDisableTiming);
    }
};

extern "C" void kernel_launch(void* const* d_in, const int* in_sizes, int n_in,
                              void* d_out, int out_size) {
    static AsyncRes ar;  // created on first (non-captured) correctness call

    const float* x  = (const float*)d_in[0];
    const int*   ei = (const int*)d_in[1];
    const float* w1 = (const float*)d_in[2];
    const float* b1 = (const float*)d_in[3];
    const float* w2 = (const float*)d_in[4];
    const float* b2 = (const float*)d_in[5];
    float* out = (float*)d_out;

    const int* row = ei;            // edge_index[0] = src
    const int* col = ei + NEDGES;   // edge_index[1] = dst

    // fork: CSR chain on s1, GEMM path on stream 0 — fully independent
    cudaEventRecord(ar.eFork, 0);
    cudaStreamWaitEvent(ar.s1, ar.eFork, 0);

    // stream 0: dense path
    w1pad_kernel<<<360, 256>>>(w1);
    gemm1_kernel<<<782, 128>>>(x);

    // stream s1: CSR build (hidden under gemm1)
    count_kernel<<<6250, 256, 0, ar.s1>>>(col);
    scan_local_kernel<<<98, 1024, 0, ar.s1>>>();      // also computes dinv
    scan_bsums_kernel<<<1, 128, 0, ar.s1>>>();
    scan_add_kernel<<<391, 256, 0, ar.s1>>>();        // also zeroes counts
    scatter_kernel<<<6250, 256, 0, ar.s1>>>(row, col);

    // join
    cudaEventRecord(ar.eJoin, ar.s1);
    cudaStreamWaitEvent(0, ar.eJoin, 0);

    // aggregations (need both paths)
    agg1_kernel<<<12500, 256>>>(b1, w2);              // fused lin2
    agg2_kernel<<<3125, 256>>>(b2, out);
}

// round 13
// speedup vs baseline: 1.3830x; 1.0572x over previous
#include <cuda_runtime.h>
#include <cuda_bf16.h>

#define NNODES 100000
#define NEDGES 1600000
#define INDIM  1433
#define HID    50
#define OUTD   7
#define KCHUNKS 45     // ceil(1433/32)

// ---------------- scratch (static device memory; zero-initialized at load) ----
__device__ int   g_counts[NNODES];        // re-zeroed by scan_add for next replay
__device__ int   g_rowptr[NNODES + 1];
__device__ int   g_cursor[NNODES];
__device__ int   g_bsums[128];
__device__ int2  g_edge[NEDGES];          // {src, bits(dinv[src])}
__device__ float g_dinv[NNODES];
__device__ __nv_bfloat16 g_h1b[NNODES * 64];  // layer-1 linear out, bf16 (pad cols stay 0)
__device__ float g_z[NNODES * 8];             // layer-2 linear out (col 7 stays 0)
__device__ float g_w1p[KCHUNKS * 2048];       // W1 pre-padded: [45][32][64]

// ---------------- ptx helpers ----------------
__device__ __forceinline__ void mma_tf32(float* c,
                                         unsigned a0, unsigned a1, unsigned a2, unsigned a3,
                                         unsigned b0, unsigned b1) {
    asm("mma.sync.aligned.m16n8k8.row.col.f32.tf32.tf32.f32 "
        "{%0,%1,%2,%3}, {%4,%5,%6,%7}, {%8,%9}, {%0,%1,%2,%3};"
        : "+f"(c[0]), "+f"(c[1]), "+f"(c[2]), "+f"(c[3])
        : "r"(a0), "r"(a1), "r"(a2), "r"(a3), "r"(b0), "r"(b1));
}

__device__ __forceinline__ void cp_async16(unsigned dst, const float4* src) {
    asm volatile("cp.async.cg.shared.global [%0], [%1], 16;" :: "r"(dst), "l"(src));
}
__device__ __forceinline__ void cp_commit() { asm volatile("cp.async.commit_group;"); }
__device__ __forceinline__ void cp_wait1() { asm volatile("cp.async.wait_group 1;"); }
__device__ __forceinline__ void cp_wait0() { asm volatile("cp.async.wait_group 0;"); }

// ---------------- W1 pre-pad: [45][32][64], zero padding ----------------
__global__ void w1pad_kernel(const float* __restrict__ w1) {
    int i = blockIdx.x * 256 + threadIdx.x;
    if (i < KCHUNKS * 2048) {
        int kc = i >> 11, rem = i & 2047;
        int kk = rem >> 6, n = rem & 63;
        int k = kc * 32 + kk;
        g_w1p[i] = (k < INDIM && n < HID) ? __ldg(&w1[k * HID + n]) : 0.f;
    }
}

// ---------------- CSR build ----------------
__global__ void count_kernel(const int* __restrict__ col) {
    int i = blockIdx.x * blockDim.x + threadIdx.x;
    if (i < NEDGES) atomicAdd(&g_counts[__ldg(&col[i])], 1);
}

// local scan of counts + dinv computation (fused)
__global__ void scan_local_kernel() {
    __shared__ int ws[32];
    int tid = threadIdx.x;
    int i = blockIdx.x * 1024 + tid;
    int v = (i < NNODES) ? g_counts[i] : 0;
    if (i < NNODES) g_dinv[i] = rsqrtf((float)(v + 1));  // +1 self loop
    int x = v;
#pragma unroll
    for (int d = 1; d < 32; d <<= 1) {
        int y = __shfl_up_sync(0xffffffffu, x, d);
        if ((tid & 31) >= d) x += y;
    }
    if ((tid & 31) == 31) ws[tid >> 5] = x;
    __syncthreads();
    if (tid < 32) {
        int w = ws[tid];
#pragma unroll
        for (int d = 1; d < 32; d <<= 1) {
            int y = __shfl_up_sync(0xffffffffu, w, d);
            if (tid >= d) w += y;
        }
        ws[tid] = w;
    }
    __syncthreads();
    int woff = (tid >= 32) ? ws[(tid >> 5) - 1] : 0;
    int incl = x + woff;
    if (i < NNODES) g_rowptr[i] = incl - v;       // local exclusive
    if (tid == 1023) g_bsums[blockIdx.x] = incl;  // block total
}

__global__ void scan_bsums_kernel() {
    __shared__ int ws[4];
    int tid = threadIdx.x;
    int v = (tid < 98) ? g_bsums[tid] : 0;
    int x = v;
#pragma unroll
    for (int d = 1; d < 32; d <<= 1) {
        int y = __shfl_up_sync(0xffffffffu, x, d);
        if ((tid & 31) >= d) x += y;
    }
    if ((tid & 31) == 31) ws[tid >> 5] = x;
    __syncthreads();
    if (tid < 4) {
        int wv = ws[tid];
#pragma unroll
        for (int d = 1; d < 4; d <<= 1) {
            int y = __shfl_up_sync(0x0000000fu, wv, d);
            if (tid >= d) wv += y;
        }
        ws[tid] = wv;
    }
    __syncthreads();
    int off = (tid >= 32) ? ws[(tid >> 5) - 1] : 0;
    if (tid < 98) g_bsums[tid] = x + off - v;
}

__global__ void scan_add_kernel() {
    int i = blockIdx.x * blockDim.x + threadIdx.x;
    if (i < NNODES) {
        int val = g_rowptr[i] + g_bsums[i >> 10];
        g_rowptr[i] = val;
        g_cursor[i] = val;
        g_counts[i] = 0;  // reset for next graph replay
    }
    if (i == 0) g_rowptr[NNODES] = NEDGES;
}

__global__ void scatter_kernel(const int* __restrict__ row, const int* __restrict__ col) {
    int i = blockIdx.x * blockDim.x + threadIdx.x;
    if (i < NEDGES) {
        int c = __ldg(&col[i]);
        int r = __ldg(&row[i]);
        int p = atomicAdd(&g_cursor[c], 1);
        g_edge[p] = make_int2(r, __float_as_int(__ldg(&g_dinv[r])));
    }
}

// ---------------- GEMM1: h1 = x @ W1 (tf32 HMMA) — R4 champion, frozen -------
// A fragments loaded DIRECTLY from gmem (no smem roundtrip).
// B double-buffered in smem via cp.async 16B (from padded g_w1p).
// 128 threads = 4 warps; block tile M=128 (warp 32 rows), N=56, K chunk 32.
#define BLD 72   // Bs ld: frag bank = (8*tg+gid) mod 32 -> conflict-free

__global__ __launch_bounds__(128, 4) void gemm1_kernel(const float* __restrict__ x) {
    __shared__ float Bs[2][32 * BLD];
    int t = threadIdx.x, lane = t & 31, w = t >> 5;
    int gid = lane >> 2, tg = lane & 3;
    int mbase = blockIdx.x * 128;
    int rw = mbase + w * 32;

    unsigned bsb = (unsigned)__cvta_generic_to_shared(&Bs[0][0]);
    const float4* w1p4 = (const float4*)g_w1p;

    float acc[14][4];  // [mt*7+nt][j]
#pragma unroll
    for (int i = 0; i < 14; i++)
#pragma unroll
        for (int j = 0; j < 4; j++) acc[i][j] = 0.f;

    // per-thread A row pointers + validity (rows: rw + mt*16 + gid, +8)
    const float* xp[4];
    bool rok[4];
#pragma unroll
    for (int mt = 0; mt < 2; mt++) {
        int r0 = rw + mt * 16 + gid;
        int r1 = r0 + 8;
        rok[mt * 2]     = r0 < NNODES;
        rok[mt * 2 + 1] = r1 < NNODES;
        xp[mt * 2]      = x + (size_t)(rok[mt * 2] ? r0 : 0) * INDIM;
        xp[mt * 2 + 1]  = x + (size_t)(rok[mt * 2 + 1] ? r1 : 0) * INDIM;
    }

    auto stageB = [&](int kc, int buf) {
        unsigned bbase = bsb + buf * (32 * BLD * 4);
#pragma unroll
        for (int i = 0; i < 4; i++) {
            int idx = (t + i * 128) * 4;          // float index in [0,2048)
            int kk = idx >> 6, n = idx & 63;
            cp_async16(bbase + (kk * BLD + n) * 4, &w1p4[kc * 512 + t + i * 128]);
        }
        cp_commit();
    };

    stageB(0, 0);

    for (int kc = 0; kc < KCHUNKS; kc++) {
        int buf = kc & 1;
        int kb = kc * 32;

        // A fragments for this chunk: direct LDG (issued early, latency hidden
        // under B wait + sync + LDS below, and by desynchronized sibling CTAs)
        float aF[2][4][4];  // [mt][k8][j]
#pragma unroll
        for (int k8 = 0; k8 < 4; k8++) {
            int c0 = kb + k8 * 8 + tg;
            bool c0ok = c0 < INDIM;
            bool c1ok = (c0 + 4) < INDIM;
#pragma unroll
            for (int mt = 0; mt < 2; mt++) {
                aF[mt][k8][0] = (rok[mt * 2]     && c0ok) ? __ldg(xp[mt * 2] + c0)         : 0.f;
                aF[mt][k8][1] = (rok[mt * 2 + 1] && c0ok) ? __ldg(xp[mt * 2 + 1] + c0)     : 0.f;
                aF[mt][k8][2] = (rok[mt * 2]     && c1ok) ? __ldg(xp[mt * 2] + c0 + 4)     : 0.f;
                aF[mt][k8][3] = (rok[mt * 2 + 1] && c1ok) ? __ldg(xp[mt * 2 + 1] + c0 + 4) : 0.f;
            }
        }

        if (kc + 1 < KCHUNKS) { stageB(kc + 1, buf ^ 1); cp_wait1(); }
        else cp_wait0();
        __syncthreads();

        const float* B = &Bs[buf][0];
#pragma unroll
        for (int k8 = 0; k8 < 4; k8++) {
            int kk = k8 * 8;
            unsigned b0[7], b1[7];
#pragma unroll
            for (int nt = 0; nt < 7; nt++) {
                b0[nt] = __float_as_uint(B[(kk + tg) * BLD + nt * 8 + gid]);
                b1[nt] = __float_as_uint(B[(kk + tg + 4) * BLD + nt * 8 + gid]);
            }
#pragma unroll
            for (int mt = 0; mt < 2; mt++) {
#pragma unroll
                for (int nt = 0; nt < 7; nt++)
                    mma_tf32(acc[mt * 7 + nt],
                             __float_as_uint(aF[mt][k8][0]), __float_as_uint(aF[mt][k8][1]),
                             __float_as_uint(aF[mt][k8][2]), __float_as_uint(aF[mt][k8][3]),
                             b0[nt], b1[nt]);
            }
        }
        __syncthreads();  // Bs[buf] free before restage in next iteration
    }

    // epilogue: write bf16 pairs (c0 in {0,2,..,48})
    unsigned* hout = (unsigned*)g_h1b;
#pragma unroll
    for (int mt = 0; mt < 2; mt++) {
#pragma unroll
        for (int nt = 0; nt < 7; nt++) {
            int c0 = nt * 8 + tg * 2;
            if (c0 < HID) {
#pragma unroll
                for (int h = 0; h < 2; h++) {
                    int r = mbase + w * 32 + mt * 16 + gid + h * 8;
                    if (r < NNODES) {
                        __nv_bfloat162 bv = __float22bfloat162_rn(
                            make_float2(acc[mt * 7 + nt][h * 2], acc[mt * 7 + nt][h * 2 + 1]));
                        hout[(size_t)r * 32 + (c0 >> 1)] = *(unsigned*)&bv;
                    }
                }
            }
        }
    }
}

// ---------------- Aggregation 1 + fused lin2 (smem transpose reduction) ------
// 1 node per warp; lane covers cols {2*lane, 2*lane+1} as one bf16x2 word.
// lin2: warp stores relu'd o1 row to its own padded smem row (row stride 68
// floats -> conflict-free strided reads), then 28 lanes = (jo 0..6)x(part 0..3)
// each sum 16 stride-4 columns, combined with TWO shfl stages (vs 5x7 butterfly).
__global__ __launch_bounds__(256) void agg1_kernel(const float* __restrict__ b1,
                                                   const float* __restrict__ w2) {
    __shared__ float w2s[64 * OUTD];   // zero-extended rows 50..63
    __shared__ float o1s[8][68];       // row stride 68 -> bank-conflict-free
    int t = threadIdx.x, lane = t & 31, w = t >> 5;
    for (int i = t; i < 64 * OUTD; i += 256)
        w2s[i] = (i < HID * OUTD) ? __ldg(&w2[i]) : 0.f;
    __syncthreads();
    int v = blockIdx.x * 8 + w;   // grid 12500 * 8 = 100000 exactly
    int s0 = __ldg(&g_rowptr[v]);
    int s1 = __ldg(&g_rowptr[v + 1]);
    float dv = __ldg(&g_dinv[v]);
    const unsigned* hb = (const unsigned*)g_h1b;

    unsigned su = __ldg(&hb[(size_t)v * 32 + lane]);
    float2 self = __bfloat1622float2(*(__nv_bfloat162*)&su);
    float ax = dv * self.x, ay = dv * self.y;
    int j = s0;
    for (; j + 3 < s1; j += 4) {
        int2 e0 = __ldg(&g_edge[j]);
        int2 e1 = __ldg(&g_edge[j + 1]);
        int2 e2 = __ldg(&g_edge[j + 2]);
        int2 e3 = __ldg(&g_edge[j + 3]);
        unsigned u0 = __ldg(&hb[(size_t)e0.x * 32 + lane]);
        unsigned u1 = __ldg(&hb[(size_t)e1.x * 32 + lane]);
        unsigned u2 = __ldg(&hb[(size_t)e2.x * 32 + lane]);
        unsigned u3 = __ldg(&hb[(size_t)e3.x * 32 + lane]);
        float2 h0 = __bfloat1622float2(*(__nv_bfloat162*)&u0);
        float2 h1v = __bfloat1622float2(*(__nv_bfloat162*)&u1);
        float2 h2 = __bfloat1622float2(*(__nv_bfloat162*)&u2);
        float2 h3 = __bfloat1622float2(*(__nv_bfloat162*)&u3);
        float w0 = __int_as_float(e0.y), w1v = __int_as_float(e1.y);
        float w2v = __int_as_float(e2.y), w3 = __int_as_float(e3.y);
        ax = fmaf(w0, h0.x, ax);   ay = fmaf(w0, h0.y, ay);
        ax = fmaf(w1v, h1v.x, ax); ay = fmaf(w1v, h1v.y, ay);
        ax = fmaf(w2v, h2.x, ax);  ay = fmaf(w2v, h2.y, ay);
        ax = fmaf(w3, h3.x, ax);   ay = fmaf(w3, h3.y, ay);
    }
    for (; j < s1; j++) {
        int2 e = __ldg(&g_edge[j]);
        unsigned u0 = __ldg(&hb[(size_t)e.x * 32 + lane]);
        float2 h0 = __bfloat1622float2(*(__nv_bfloat162*)&u0);
        float we = __int_as_float(e.y);
        ax = fmaf(we, h0.x, ax);
        ay = fmaf(we, h0.y, ay);
    }
    int f0 = 2 * lane, f1 = 2 * lane + 1;
    float o1x = (f0 < HID) ? fmaxf(fmaf(dv, ax, __ldg(&b1[f0])), 0.f) : 0.f;
    float o1y = (f1 < HID) ? fmaxf(fmaf(dv, ay, __ldg(&b1[f1])), 0.f) : 0.f;

    // store own o1 row (64 cols incl. zero pad), then strided dot from smem
    *(float2*)&o1s[w][2 * lane] = make_float2(o1x, o1y);
    __syncwarp();
    int jo = lane >> 2;        // 0..7
    int part = lane & 3;       // 0..3
    if (jo < 7) {              // lanes 0..27 active (aligned groups of 4)
        float p = 0.f;
#pragma unroll
        for (int i = 0; i < 16; i++) {
            int f = part + 4 * i;
            p = fmaf(o1s[w][f], w2s[f * OUTD + jo], p);
        }
        p += __shfl_xor_sync(0x0fffffffu, p, 1);
        p += __shfl_xor_sync(0x0fffffffu, p, 2);
        if (part == 0) g_z[(size_t)v * 8 + jo] = p;
    }
}

// ---------------- Aggregation 2 (+b2, sigmoid; R6 champion form) -------------
__global__ __launch_bounds__(256) void agg2_kernel(const float* __restrict__ b2,
                                                   float* __restrict__ out) {
    int t = threadIdx.x;
    int jj = t & 7;
    int v = blockIdx.x * 32 + (t >> 3);
    int s0 = __ldg(&g_rowptr[v]);
    int s1 = __ldg(&g_rowptr[v + 1]);
    float dv = __ldg(&g_dinv[v]);
    float acc = dv * __ldg(&g_z[(size_t)v * 8 + jj]);
    int j = s0;
    for (; j + 3 < s1; j += 4) {
        int2 e0 = __ldg(&g_edge[j]);
        int2 e1 = __ldg(&g_edge[j + 1]);
        int2 e2 = __ldg(&g_edge[j + 2]);
        int2 e3 = __ldg(&g_edge[j + 3]);
        acc = fmaf(__int_as_float(e0.y), __ldg(&g_z[(size_t)e0.x * 8 + jj]), acc);
        acc = fmaf(__int_as_float(e1.y), __ldg(&g_z[(size_t)e1.x * 8 + jj]), acc);
        acc = fmaf(__int_as_float(e2.y), __ldg(&g_z[(size_t)e2.x * 8 + jj]), acc);
        acc = fmaf(__int_as_float(e3.y), __ldg(&g_z[(size_t)e3.x * 8 + jj]), acc);
    }
    for (; j < s1; j++) {
        int2 e = __ldg(&g_edge[j]);
        acc = fmaf(__int_as_float(e.y), __ldg(&g_z[(size_t)e.x * 8 + jj]), acc);
    }
    if (jj < OUTD) {
        float zz = fmaf(dv, acc, __ldg(&b2[jj]));
        out[v * OUTD + jj] = 1.f / (1.f + __expf(-zz));
    }
}

// ---------------- launch (two-stream fork/join for CSR || GEMM overlap) ------
struct AsyncRes {
    cudaStream_t s1;
    cudaEvent_t eFork, eJoin;
    AsyncRes() {
        cudaStreamCreateWithFlags(&s1, cudaStreamNonBlocking);
        cudaEventCreateWithFlags(&eFork, cudaEventDisableTiming);
        cudaEventCreateWithFlags(&eJoin, cudaEventDisableTiming);
    }
};

extern "C" void kernel_launch(void* const* d_in, const int* in_sizes, int n_in,
                              void* d_out, int out_size) {
    static AsyncRes ar;  // created on first (non-captured) correctness call

    const float* x  = (const float*)d_in[0];
    const int*   ei = (const int*)d_in[1];
    const float* w1 = (const float*)d_in[2];
    const float* b1 = (const float*)d_in[3];
    const float* w2 = (const float*)d_in[4];
    const float* b2 = (const float*)d_in[5];
    float* out = (float*)d_out;

    const int* row = ei;            // edge_index[0] = src
    const int* col = ei + NEDGES;   // edge_index[1] = dst

    // fork: CSR chain on s1, GEMM path on stream 0 — fully independent
    cudaEventRecord(ar.eFork, 0);
    cudaStreamWaitEvent(ar.s1, ar.eFork, 0);

    // stream 0: dense path
    w1pad_kernel<<<360, 256>>>(w1);
    gemm1_kernel<<<782, 128>>>(x);

    // stream s1: CSR build (hidden under gemm1)
    count_kernel<<<6250, 256, 0, ar.s1>>>(col);
    scan_local_kernel<<<98, 1024, 0, ar.s1>>>();      // also computes dinv
    scan_bsums_kernel<<<1, 128, 0, ar.s1>>>();
    scan_add_kernel<<<391, 256, 0, ar.s1>>>();        // also zeroes counts
    scatter_kernel<<<6250, 256, 0, ar.s1>>>(row, col);

    // join
    cudaEventRecord(ar.eJoin, ar.s1);
    cudaStreamWaitEvent(0, ar.eJoin, 0);

    // aggregations (need both paths)
    agg1_kernel<<<12500, 256>>>(b1, w2);              // fused lin2
    agg2_kernel<<<3125, 256>>>(b2, out);
}

// round 14
// speedup vs baseline: 1.4435x; 1.0438x over previous
#include <cuda_runtime.h>
#include <cuda_bf16.h>

#define NNODES 100000
#define NEDGES 1600000
#define INDIM  1433
#define HID    50
#define OUTD   7
#define KCHUNKS 45     // ceil(1433/32)

// ---------------- scratch (static device memory; zero-initialized at load) ----
__device__ int   g_counts[NNODES];        // re-zeroed by scan_add for next replay
__device__ int   g_rowptr[NNODES + 1];
__device__ int   g_cursor[NNODES];
__device__ int   g_bsums[128];
__device__ int2  g_edge[NEDGES];          // {src, bits(dinv[src])}
__device__ float g_dinv[NNODES];
__device__ __nv_bfloat16 g_h1b[NNODES * 64];  // layer-1 linear out, bf16 (pad cols stay 0)
__device__ float g_z[NNODES * 8];             // layer-2 linear out (col 7 stays 0)
__device__ float g_w1p[KCHUNKS * 2048];       // W1 pre-padded: [45][32][64]

// ---------------- ptx helpers ----------------
__device__ __forceinline__ void mma_tf32(float* c,
                                         unsigned a0, unsigned a1, unsigned a2, unsigned a3,
                                         unsigned b0, unsigned b1) {
    asm("mma.sync.aligned.m16n8k8.row.col.f32.tf32.tf32.f32 "
        "{%0,%1,%2,%3}, {%4,%5,%6,%7}, {%8,%9}, {%0,%1,%2,%3};"
        : "+f"(c[0]), "+f"(c[1]), "+f"(c[2]), "+f"(c[3])
        : "r"(a0), "r"(a1), "r"(a2), "r"(a3), "r"(b0), "r"(b1));
}

__device__ __forceinline__ void cp_async16(unsigned dst, const float4* src) {
    asm volatile("cp.async.cg.shared.global [%0], [%1], 16;" :: "r"(dst), "l"(src));
}
__device__ __forceinline__ void cp_commit() { asm volatile("cp.async.commit_group;"); }
__device__ __forceinline__ void cp_wait1() { asm volatile("cp.async.wait_group 1;"); }
__device__ __forceinline__ void cp_wait0() { asm volatile("cp.async.wait_group 0;"); }

// unpack uint2 (4 bf16) and accumulate with weight
__device__ __forceinline__ void acc_bf16x4(float* a, uint2 u, float wq) {
    float2 lo = __bfloat1622float2(*(__nv_bfloat162*)&u.x);
    float2 hi = __bfloat1622float2(*(__nv_bfloat162*)&u.y);
    a[0] = fmaf(wq, lo.x, a[0]);
    a[1] = fmaf(wq, lo.y, a[1]);
    a[2] = fmaf(wq, hi.x, a[2]);
    a[3] = fmaf(wq, hi.y, a[3]);
}

// ---------------- W1 pre-pad: [45][32][64], zero padding ----------------
__global__ void w1pad_kernel(const float* __restrict__ w1) {
    int i = blockIdx.x * 256 + threadIdx.x;
    if (i < KCHUNKS * 2048) {
        int kc = i >> 11, rem = i & 2047;
        int kk = rem >> 6, n = rem & 63;
        int k = kc * 32 + kk;
        g_w1p[i] = (k < INDIM && n < HID) ? __ldg(&w1[k * HID + n]) : 0.f;
    }
}

// ---------------- CSR build ----------------
__global__ void count_kernel(const int* __restrict__ col) {
    int i = blockIdx.x * blockDim.x + threadIdx.x;
    if (i < NEDGES) atomicAdd(&g_counts[__ldg(&col[i])], 1);
}

// local scan of counts + dinv computation (fused)
__global__ void scan_local_kernel() {
    __shared__ int ws[32];
    int tid = threadIdx.x;
    int i = blockIdx.x * 1024 + tid;
    int v = (i < NNODES) ? g_counts[i] : 0;
    if (i < NNODES) g_dinv[i] = rsqrtf((float)(v + 1));  // +1 self loop
    int x = v;
#pragma unroll
    for (int d = 1; d < 32; d <<= 1) {
        int y = __shfl_up_sync(0xffffffffu, x, d);
        if ((tid & 31) >= d) x += y;
    }
    if ((tid & 31) == 31) ws[tid >> 5] = x;
    __syncthreads();
    if (tid < 32) {
        int w = ws[tid];
#pragma unroll
        for (int d = 1; d < 32; d <<= 1) {
            int y = __shfl_up_sync(0xffffffffu, w, d);
            if (tid >= d) w += y;
        }
        ws[tid] = w;
    }
    __syncthreads();
    int woff = (tid >= 32) ? ws[(tid >> 5) - 1] : 0;
    int incl = x + woff;
    if (i < NNODES) g_rowptr[i] = incl - v;       // local exclusive
    if (tid == 1023) g_bsums[blockIdx.x] = incl;  // block total
}

__global__ void scan_bsums_kernel() {
    __shared__ int ws[4];
    int tid = threadIdx.x;
    int v = (tid < 98) ? g_bsums[tid] : 0;
    int x = v;
#pragma unroll
    for (int d = 1; d < 32; d <<= 1) {
        int y = __shfl_up_sync(0xffffffffu, x, d);
        if ((tid & 31) >= d) x += y;
    }
    if ((tid & 31) == 31) ws[tid >> 5] = x;
    __syncthreads();
    if (tid < 4) {
        int wv = ws[tid];
#pragma unroll
        for (int d = 1; d < 4; d <<= 1) {
            int y = __shfl_up_sync(0x0000000fu, wv, d);
            if (tid >= d) wv += y;
        }
        ws[tid] = wv;
    }
    __syncthreads();
    int off = (tid >= 32) ? ws[(tid >> 5) - 1] : 0;
    if (tid < 98) g_bsums[tid] = x + off - v;
}

__global__ void scan_add_kernel() {
    int i = blockIdx.x * blockDim.x + threadIdx.x;
    if (i < NNODES) {
        int val = g_rowptr[i] + g_bsums[i >> 10];
        g_rowptr[i] = val;
        g_cursor[i] = val;
        g_counts[i] = 0;  // reset for next graph replay
    }
    if (i == 0) g_rowptr[NNODES] = NEDGES;
}

__global__ void scatter_kernel(const int* __restrict__ row, const int* __restrict__ col) {
    int i = blockIdx.x * blockDim.x + threadIdx.x;
    if (i < NEDGES) {
        int c = __ldg(&col[i]);
        int r = __ldg(&row[i]);
        int p = atomicAdd(&g_cursor[c], 1);
        g_edge[p] = make_int2(r, __float_as_int(__ldg(&g_dinv[r])));
    }
}

// ---------------- GEMM1: h1 = x @ W1 (tf32 HMMA) — R4 champion, frozen -------
// A fragments loaded DIRECTLY from gmem (no smem roundtrip).
// B double-buffered in smem via cp.async 16B (from padded g_w1p).
// 128 threads = 4 warps; block tile M=128 (warp 32 rows), N=56, K chunk 32.
#define BLD 72   // Bs ld: frag bank = (8*tg+gid) mod 32 -> conflict-free

__global__ __launch_bounds__(128, 4) void gemm1_kernel(const float* __restrict__ x) {
    __shared__ float Bs[2][32 * BLD];
    int t = threadIdx.x, lane = t & 31, w = t >> 5;
    int gid = lane >> 2, tg = lane & 3;
    int mbase = blockIdx.x * 128;
    int rw = mbase + w * 32;

    unsigned bsb = (unsigned)__cvta_generic_to_shared(&Bs[0][0]);
    const float4* w1p4 = (const float4*)g_w1p;

    float acc[14][4];  // [mt*7+nt][j]
#pragma unroll
    for (int i = 0; i < 14; i++)
#pragma unroll
        for (int j = 0; j < 4; j++) acc[i][j] = 0.f;

    // per-thread A row pointers + validity (rows: rw + mt*16 + gid, +8)
    const float* xp[4];
    bool rok[4];
#pragma unroll
    for (int mt = 0; mt < 2; mt++) {
        int r0 = rw + mt * 16 + gid;
        int r1 = r0 + 8;
        rok[mt * 2]     = r0 < NNODES;
        rok[mt * 2 + 1] = r1 < NNODES;
        xp[mt * 2]      = x + (size_t)(rok[mt * 2] ? r0 : 0) * INDIM;
        xp[mt * 2 + 1]  = x + (size_t)(rok[mt * 2 + 1] ? r1 : 0) * INDIM;
    }

    auto stageB = [&](int kc, int buf) {
        unsigned bbase = bsb + buf * (32 * BLD * 4);
#pragma unroll
        for (int i = 0; i < 4; i++) {
            int idx = (t + i * 128) * 4;          // float index in [0,2048)
            int kk = idx >> 6, n = idx & 63;
            cp_async16(bbase + (kk * BLD + n) * 4, &w1p4[kc * 512 + t + i * 128]);
        }
        cp_commit();
    };

    stageB(0, 0);

    for (int kc = 0; kc < KCHUNKS; kc++) {
        int buf = kc & 1;
        int kb = kc * 32;

        // A fragments for this chunk: direct LDG (issued early, latency hidden
        // under B wait + sync + LDS below, and by desynchronized sibling CTAs)
        float aF[2][4][4];  // [mt][k8][j]
#pragma unroll
        for (int k8 = 0; k8 < 4; k8++) {
            int c0 = kb + k8 * 8 + tg;
            bool c0ok = c0 < INDIM;
            bool c1ok = (c0 + 4) < INDIM;
#pragma unroll
            for (int mt = 0; mt < 2; mt++) {
                aF[mt][k8][0] = (rok[mt * 2]     && c0ok) ? __ldg(xp[mt * 2] + c0)         : 0.f;
                aF[mt][k8][1] = (rok[mt * 2 + 1] && c0ok) ? __ldg(xp[mt * 2 + 1] + c0)     : 0.f;
                aF[mt][k8][2] = (rok[mt * 2]     && c1ok) ? __ldg(xp[mt * 2] + c0 + 4)     : 0.f;
                aF[mt][k8][3] = (rok[mt * 2 + 1] && c1ok) ? __ldg(xp[mt * 2 + 1] + c0 + 4) : 0.f;
            }
        }

        if (kc + 1 < KCHUNKS) { stageB(kc + 1, buf ^ 1); cp_wait1(); }
        else cp_wait0();
        __syncthreads();

        const float* B = &Bs[buf][0];
#pragma unroll
        for (int k8 = 0; k8 < 4; k8++) {
            int kk = k8 * 8;
            unsigned b0[7], b1[7];
#pragma unroll
            for (int nt = 0; nt < 7; nt++) {
                b0[nt] = __float_as_uint(B[(kk + tg) * BLD + nt * 8 + gid]);
                b1[nt] = __float_as_uint(B[(kk + tg + 4) * BLD + nt * 8 + gid]);
            }
#pragma unroll
            for (int mt = 0; mt < 2; mt++) {
#pragma unroll
                for (int nt = 0; nt < 7; nt++)
                    mma_tf32(acc[mt * 7 + nt],
                             __float_as_uint(aF[mt][k8][0]), __float_as_uint(aF[mt][k8][1]),
                             __float_as_uint(aF[mt][k8][2]), __float_as_uint(aF[mt][k8][3]),
                             b0[nt], b1[nt]);
            }
        }
        __syncthreads();  // Bs[buf] free before restage in next iteration
    }

    // epilogue: write bf16 pairs (c0 in {0,2,..,48})
    unsigned* hout = (unsigned*)g_h1b;
#pragma unroll
    for (int mt = 0; mt < 2; mt++) {
#pragma unroll
        for (int nt = 0; nt < 7; nt++) {
            int c0 = nt * 8 + tg * 2;
            if (c0 < HID) {
#pragma unroll
                for (int h = 0; h < 2; h++) {
                    int r = mbase + w * 32 + mt * 16 + gid + h * 8;
                    if (r < NNODES) {
                        __nv_bfloat162 bv = __float22bfloat162_rn(
                            make_float2(acc[mt * 7 + nt][h * 2], acc[mt * 7 + nt][h * 2 + 1]));
                        hout[(size_t)r * 32 + (c0 >> 1)] = *(unsigned*)&bv;
                    }
                }
            }
        }
    }
}

// ---------------- Aggregation 1 + fused lin2 (1 node per HALF-warp) ----------
// 16 lanes per node; lane covers cols [4*l16, 4*l16+4) as one uint2 (4 bf16).
// Per 4-edge iteration one instruction stream serves 2 nodes: LDG issues per
// edge halved, gather MLP per warp doubled. lin2 via smem transpose (o1s row
// stride 68 -> conflict-free), 14 active lanes/node, one shfl stage.
__global__ __launch_bounds__(256) void agg1_kernel(const float* __restrict__ b1,
                                                   const float* __restrict__ w2) {
    __shared__ float w2s[64 * OUTD];   // zero-extended rows 50..63
    __shared__ float o1s[16][68];      // row stride 68 -> bank-conflict-free
    int t = threadIdx.x;
    int hw = t >> 4;        // node slot 0..15
    int l16 = t & 15;
    for (int i = t; i < 64 * OUTD; i += 256)
        w2s[i] = (i < HID * OUTD) ? __ldg(&w2[i]) : 0.f;
    __syncthreads();
    int v = blockIdx.x * 16 + hw;   // grid 6250 * 16 = 100000 exactly
    int s0 = __ldg(&g_rowptr[v]);
    int s1 = __ldg(&g_rowptr[v + 1]);
    float dv = __ldg(&g_dinv[v]);
    const uint2* hb = (const uint2*)g_h1b;   // 16 uint2 per row

    float a[4] = {0.f, 0.f, 0.f, 0.f};
    uint2 su = __ldg(&hb[(size_t)v * 16 + l16]);
    acc_bf16x4(a, su, dv);

    int j = s0;
    for (; j + 3 < s1; j += 4) {
        int2 e0 = __ldg(&g_edge[j]);
        int2 e1 = __ldg(&g_edge[j + 1]);
        int2 e2 = __ldg(&g_edge[j + 2]);
        int2 e3 = __ldg(&g_edge[j + 3]);
        uint2 u0 = __ldg(&hb[(size_t)e0.x * 16 + l16]);
        uint2 u1 = __ldg(&hb[(size_t)e1.x * 16 + l16]);
        uint2 u2 = __ldg(&hb[(size_t)e2.x * 16 + l16]);
        uint2 u3 = __ldg(&hb[(size_t)e3.x * 16 + l16]);
        acc_bf16x4(a, u0, __int_as_float(e0.y));
        acc_bf16x4(a, u1, __int_as_float(e1.y));
        acc_bf16x4(a, u2, __int_as_float(e2.y));
        acc_bf16x4(a, u3, __int_as_float(e3.y));
    }
    for (; j < s1; j++) {
        int2 e = __ldg(&g_edge[j]);
        uint2 u = __ldg(&hb[(size_t)e.x * 16 + l16]);
        acc_bf16x4(a, u, __int_as_float(e.y));
    }

    // relu + b1 for the 4 covered cols; pad cols (f >= HID) forced to 0
    float4 o1v;
    {
        float* o = (float*)&o1v;
#pragma unroll
        for (int c = 0; c < 4; c++) {
            int f = 4 * l16 + c;
            o[c] = (f < HID) ? fmaxf(fmaf(dv, a[c], __ldg(&b1[f])), 0.f) : 0.f;
        }
    }
    *(float4*)&o1s[hw][4 * l16] = o1v;
    __syncwarp();

    // reduction: jo = l16>>1 (0..7), part = l16&1; each active lane sums 32
    // stride-2 columns; one shfl stage combines the two parts.
    int jo = l16 >> 1;
    int part = l16 & 1;
    float p = 0.f;
    if (jo < 7) {
#pragma unroll
        for (int i = 0; i < 32; i++) {
            int f = part + 2 * i;
            p = fmaf(o1s[hw][f], w2s[f * OUTD + jo], p);
        }
    }
    p += __shfl_xor_sync(0xffffffffu, p, 1);
    if (jo < 7 && part == 0) g_z[(size_t)v * 8 + jo] = p;
}

// ---------------- Aggregation 2 (+b2, sigmoid; R6 champion form) -------------
__global__ __launch_bounds__(256) void agg2_kernel(const float* __restrict__ b2,
                                                   float* __restrict__ out) {
    int t = threadIdx.x;
    int jj = t & 7;
    int v = blockIdx.x * 32 + (t >> 3);
    int s0 = __ldg(&g_rowptr[v]);
    int s1 = __ldg(&g_rowptr[v + 1]);
    float dv = __ldg(&g_dinv[v]);
    float acc = dv * __ldg(&g_z[(size_t)v * 8 + jj]);
    int j = s0;
    for (; j + 3 < s1; j += 4) {
        int2 e0 = __ldg(&g_edge[j]);
        int2 e1 = __ldg(&g_edge[j + 1]);
        int2 e2 = __ldg(&g_edge[j + 2]);
        int2 e3 = __ldg(&g_edge[j + 3]);
        acc = fmaf(__int_as_float(e0.y), __ldg(&g_z[(size_t)e0.x * 8 + jj]), acc);
        acc = fmaf(__int_as_float(e1.y), __ldg(&g_z[(size_t)e1.x * 8 + jj]), acc);
        acc = fmaf(__int_as_float(e2.y), __ldg(&g_z[(size_t)e2.x * 8 + jj]), acc);
        acc = fmaf(__int_as_float(e3.y), __ldg(&g_z[(size_t)e3.x * 8 + jj]), acc);
    }
    for (; j < s1; j++) {
        int2 e = __ldg(&g_edge[j]);
        acc = fmaf(__int_as_float(e.y), __ldg(&g_z[(size_t)e.x * 8 + jj]), acc);
    }
    if (jj < OUTD) {
        float zz = fmaf(dv, acc, __ldg(&b2[jj]));
        out[v * OUTD + jj] = 1.f / (1.f + __expf(-zz));
    }
}

// ---------------- launch (two-stream fork/join for CSR || GEMM overlap) ------
struct AsyncRes {
    cudaStream_t s1;
    cudaEvent_t eFork, eJoin;
    AsyncRes() {
        cudaStreamCreateWithFlags(&s1, cudaStreamNonBlocking);
        cudaEventCreateWithFlags(&eFork, cudaEventDisableTiming);
        cudaEventCreateWithFlags(&eJoin, cudaEventDisableTiming);
    }
};

extern "C" void kernel_launch(void* const* d_in, const int* in_sizes, int n_in,
                              void* d_out, int out_size) {
    static AsyncRes ar;  // created on first (non-captured) correctness call

    const float* x  = (const float*)d_in[0];
    const int*   ei = (const int*)d_in[1];
    const float* w1 = (const float*)d_in[2];
    const float* b1 = (const float*)d_in[3];
    const float* w2 = (const float*)d_in[4];
    const float* b2 = (const float*)d_in[5];
    float* out = (float*)d_out;

    const int* row = ei;            // edge_index[0] = src
    const int* col = ei + NEDGES;   // edge_index[1] = dst

    // fork: CSR chain on s1, GEMM path on stream 0 — fully independent
    cudaEventRecord(ar.eFork, 0);
    cudaStreamWaitEvent(ar.s1, ar.eFork, 0);

    // stream 0: dense path
    w1pad_kernel<<<360, 256>>>(w1);
    gemm1_kernel<<<782, 128>>>(x);

    // stream s1: CSR build (hidden under gemm1)
    count_kernel<<<6250, 256, 0, ar.s1>>>(col);
    scan_local_kernel<<<98, 1024, 0, ar.s1>>>();      // also computes dinv
    scan_bsums_kernel<<<1, 128, 0, ar.s1>>>();
    scan_add_kernel<<<391, 256, 0, ar.s1>>>();        // also zeroes counts
    scatter_kernel<<<6250, 256, 0, ar.s1>>>(row, col);

    // join
    cudaEventRecord(ar.eJoin, ar.s1);
    cudaStreamWaitEvent(0, ar.eJoin, 0);

    // aggregations (need both paths)
    agg1_kernel<<<6250, 256>>>(b1, w2);               // fused lin2, 16 nodes/block
    agg2_kernel<<<3125, 256>>>(b2, out);
}

// round 15
// speedup vs baseline: 1.4594x; 1.0110x over previous
#include <cuda_runtime.h>
#include <cuda_bf16.h>

#define NNODES 100000
#define NEDGES 1600000
#define INDIM  1433
#define HID    50
#define OUTD   7
#define KCHUNKS 45     // ceil(1433/32)

// ---------------- scratch (static device memory; zero-initialized at load) ----
__device__ int   g_counts[NNODES];        // re-zeroed by scan_add for next replay
__device__ int   g_rowptr[NNODES + 1];
__device__ int   g_cursor[NNODES];
__device__ int   g_bsums[128];
__device__ int2  g_edge[NEDGES];          // {src, bits(dinv[src])}
__device__ float g_dinv[NNODES];
__device__ __nv_bfloat16 g_h1b[NNODES * 64];  // layer-1 linear out, bf16 (pad cols stay 0)
__device__ float g_z[NNODES * 8];             // layer-2 linear out (col 7 stays 0)
__device__ float g_w1p[KCHUNKS * 2048];       // W1 pre-padded: [45][32][64]

// ---------------- ptx helpers ----------------
__device__ __forceinline__ void mma_tf32(float* c,
                                         unsigned a0, unsigned a1, unsigned a2, unsigned a3,
                                         unsigned b0, unsigned b1) {
    asm("mma.sync.aligned.m16n8k8.row.col.f32.tf32.tf32.f32 "
        "{%0,%1,%2,%3}, {%4,%5,%6,%7}, {%8,%9}, {%0,%1,%2,%3};"
        : "+f"(c[0]), "+f"(c[1]), "+f"(c[2]), "+f"(c[3])
        : "r"(a0), "r"(a1), "r"(a2), "r"(a3), "r"(b0), "r"(b1));
}

__device__ __forceinline__ void cp_async16(unsigned dst, const float4* src) {
    asm volatile("cp.async.cg.shared.global [%0], [%1], 16;" :: "r"(dst), "l"(src));
}
__device__ __forceinline__ void cp_commit() { asm volatile("cp.async.commit_group;"); }
__device__ __forceinline__ void cp_wait1() { asm volatile("cp.async.wait_group 1;"); }
__device__ __forceinline__ void cp_wait0() { asm volatile("cp.async.wait_group 0;"); }

// unpack uint4 (8 bf16) and accumulate with weight
__device__ __forceinline__ void acc_bf16x8(float* a, uint4 u, float wq) {
    float2 p0 = __bfloat1622float2(*(__nv_bfloat162*)&u.x);
    float2 p1 = __bfloat1622float2(*(__nv_bfloat162*)&u.y);
    float2 p2 = __bfloat1622float2(*(__nv_bfloat162*)&u.z);
    float2 p3 = __bfloat1622float2(*(__nv_bfloat162*)&u.w);
    a[0] = fmaf(wq, p0.x, a[0]);
    a[1] = fmaf(wq, p0.y, a[1]);
    a[2] = fmaf(wq, p1.x, a[2]);
    a[3] = fmaf(wq, p1.y, a[3]);
    a[4] = fmaf(wq, p2.x, a[4]);
    a[5] = fmaf(wq, p2.y, a[5]);
    a[6] = fmaf(wq, p3.x, a[6]);
    a[7] = fmaf(wq, p3.y, a[7]);
}

// ---------------- W1 pre-pad: [45][32][64], zero padding ----------------
__global__ void w1pad_kernel(const float* __restrict__ w1) {
    int i = blockIdx.x * 256 + threadIdx.x;
    if (i < KCHUNKS * 2048) {
        int kc = i >> 11, rem = i & 2047;
        int kk = rem >> 6, n = rem & 63;
        int k = kc * 32 + kk;
        g_w1p[i] = (k < INDIM && n < HID) ? __ldg(&w1[k * HID + n]) : 0.f;
    }
}

// ---------------- CSR build ----------------
__global__ void count_kernel(const int* __restrict__ col) {
    int i = blockIdx.x * blockDim.x + threadIdx.x;
    if (i < NEDGES) atomicAdd(&g_counts[__ldg(&col[i])], 1);
}

// local scan of counts + dinv computation (fused)
__global__ void scan_local_kernel() {
    __shared__ int ws[32];
    int tid = threadIdx.x;
    int i = blockIdx.x * 1024 + tid;
    int v = (i < NNODES) ? g_counts[i] : 0;
    if (i < NNODES) g_dinv[i] = rsqrtf((float)(v + 1));  // +1 self loop
    int x = v;
#pragma unroll
    for (int d = 1; d < 32; d <<= 1) {
        int y = __shfl_up_sync(0xffffffffu, x, d);
        if ((tid & 31) >= d) x += y;
    }
    if ((tid & 31) == 31) ws[tid >> 5] = x;
    __syncthreads();
    if (tid < 32) {
        int w = ws[tid];
#pragma unroll
        for (int d = 1; d < 32; d <<= 1) {
            int y = __shfl_up_sync(0xffffffffu, w, d);
            if (tid >= d) w += y;
        }
        ws[tid] = w;
    }
    __syncthreads();
    int woff = (tid >= 32) ? ws[(tid >> 5) - 1] : 0;
    int incl = x + woff;
    if (i < NNODES) g_rowptr[i] = incl - v;       // local exclusive
    if (tid == 1023) g_bsums[blockIdx.x] = incl;  // block total
}

__global__ void scan_bsums_kernel() {
    __shared__ int ws[4];
    int tid = threadIdx.x;
    int v = (tid < 98) ? g_bsums[tid] : 0;
    int x = v;
#pragma unroll
    for (int d = 1; d < 32; d <<= 1) {
        int y = __shfl_up_sync(0xffffffffu, x, d);
        if ((tid & 31) >= d) x += y;
    }
    if ((tid & 31) == 31) ws[tid >> 5] = x;
    __syncthreads();
    if (tid < 4) {
        int wv = ws[tid];
#pragma unroll
        for (int d = 1; d < 4; d <<= 1) {
            int y = __shfl_up_sync(0x0000000fu, wv, d);
            if (tid >= d) wv += y;
        }
        ws[tid] = wv;
    }
    __syncthreads();
    int off = (tid >= 32) ? ws[(tid >> 5) - 1] : 0;
    if (tid < 98) g_bsums[tid] = x + off - v;
}

__global__ void scan_add_kernel() {
    int i = blockIdx.x * blockDim.x + threadIdx.x;
    if (i < NNODES) {
        int val = g_rowptr[i] + g_bsums[i >> 10];
        g_rowptr[i] = val;
        g_cursor[i] = val;
        g_counts[i] = 0;  // reset for next graph replay
    }
    if (i == 0) g_rowptr[NNODES] = NEDGES;
}

__global__ void scatter_kernel(const int* __restrict__ row, const int* __restrict__ col) {
    int i = blockIdx.x * blockDim.x + threadIdx.x;
    if (i < NEDGES) {
        int c = __ldg(&col[i]);
        int r = __ldg(&row[i]);
        int p = atomicAdd(&g_cursor[c], 1);
        g_edge[p] = make_int2(r, __float_as_int(__ldg(&g_dinv[r])));
    }
}

// ---------------- GEMM1: h1 = x @ W1 (tf32 HMMA) — R4 champion, frozen -------
// A fragments loaded DIRECTLY from gmem (no smem roundtrip).
// B double-buffered in smem via cp.async 16B (from padded g_w1p).
// 128 threads = 4 warps; block tile M=128 (warp 32 rows), N=56, K chunk 32.
#define BLD 72   // Bs ld: frag bank = (8*tg+gid) mod 32 -> conflict-free

__global__ __launch_bounds__(128, 4) void gemm1_kernel(const float* __restrict__ x) {
    __shared__ float Bs[2][32 * BLD];
    int t = threadIdx.x, lane = t & 31, w = t >> 5;
    int gid = lane >> 2, tg = lane & 3;
    int mbase = blockIdx.x * 128;
    int rw = mbase + w * 32;

    unsigned bsb = (unsigned)__cvta_generic_to_shared(&Bs[0][0]);
    const float4* w1p4 = (const float4*)g_w1p;

    float acc[14][4];  // [mt*7+nt][j]
#pragma unroll
    for (int i = 0; i < 14; i++)
#pragma unroll
        for (int j = 0; j < 4; j++) acc[i][j] = 0.f;

    // per-thread A row pointers + validity (rows: rw + mt*16 + gid, +8)
    const float* xp[4];
    bool rok[4];
#pragma unroll
    for (int mt = 0; mt < 2; mt++) {
        int r0 = rw + mt * 16 + gid;
        int r1 = r0 + 8;
        rok[mt * 2]     = r0 < NNODES;
        rok[mt * 2 + 1] = r1 < NNODES;
        xp[mt * 2]      = x + (size_t)(rok[mt * 2] ? r0 : 0) * INDIM;
        xp[mt * 2 + 1]  = x + (size_t)(rok[mt * 2 + 1] ? r1 : 0) * INDIM;
    }

    auto stageB = [&](int kc, int buf) {
        unsigned bbase = bsb + buf * (32 * BLD * 4);
#pragma unroll
        for (int i = 0; i < 4; i++) {
            int idx = (t + i * 128) * 4;          // float index in [0,2048)
            int kk = idx >> 6, n = idx & 63;
            cp_async16(bbase + (kk * BLD + n) * 4, &w1p4[kc * 512 + t + i * 128]);
        }
        cp_commit();
    };

    stageB(0, 0);

    for (int kc = 0; kc < KCHUNKS; kc++) {
        int buf = kc & 1;
        int kb = kc * 32;

        // A fragments for this chunk: direct LDG (issued early, latency hidden
        // under B wait + sync + LDS below, and by desynchronized sibling CTAs)
        float aF[2][4][4];  // [mt][k8][j]
#pragma unroll
        for (int k8 = 0; k8 < 4; k8++) {
            int c0 = kb + k8 * 8 + tg;
            bool c0ok = c0 < INDIM;
            bool c1ok = (c0 + 4) < INDIM;
#pragma unroll
            for (int mt = 0; mt < 2; mt++) {
                aF[mt][k8][0] = (rok[mt * 2]     && c0ok) ? __ldg(xp[mt * 2] + c0)         : 0.f;
                aF[mt][k8][1] = (rok[mt * 2 + 1] && c0ok) ? __ldg(xp[mt * 2 + 1] + c0)     : 0.f;
                aF[mt][k8][2] = (rok[mt * 2]     && c1ok) ? __ldg(xp[mt * 2] + c0 + 4)     : 0.f;
                aF[mt][k8][3] = (rok[mt * 2 + 1] && c1ok) ? __ldg(xp[mt * 2 + 1] + c0 + 4) : 0.f;
            }
        }

        if (kc + 1 < KCHUNKS) { stageB(kc + 1, buf ^ 1); cp_wait1(); }
        else cp_wait0();
        __syncthreads();

        const float* B = &Bs[buf][0];
#pragma unroll
        for (int k8 = 0; k8 < 4; k8++) {
            int kk = k8 * 8;
            unsigned b0[7], b1[7];
#pragma unroll
            for (int nt = 0; nt < 7; nt++) {
                b0[nt] = __float_as_uint(B[(kk + tg) * BLD + nt * 8 + gid]);
                b1[nt] = __float_as_uint(B[(kk + tg + 4) * BLD + nt * 8 + gid]);
            }
#pragma unroll
            for (int mt = 0; mt < 2; mt++) {
#pragma unroll
                for (int nt = 0; nt < 7; nt++)
                    mma_tf32(acc[mt * 7 + nt],
                             __float_as_uint(aF[mt][k8][0]), __float_as_uint(aF[mt][k8][1]),
                             __float_as_uint(aF[mt][k8][2]), __float_as_uint(aF[mt][k8][3]),
                             b0[nt], b1[nt]);
            }
        }
        __syncthreads();  // Bs[buf] free before restage in next iteration
    }

    // epilogue: write bf16 pairs (c0 in {0,2,..,48})
    unsigned* hout = (unsigned*)g_h1b;
#pragma unroll
    for (int mt = 0; mt < 2; mt++) {
#pragma unroll
        for (int nt = 0; nt < 7; nt++) {
            int c0 = nt * 8 + tg * 2;
            if (c0 < HID) {
#pragma unroll
                for (int h = 0; h < 2; h++) {
                    int r = mbase + w * 32 + mt * 16 + gid + h * 8;
                    if (r < NNODES) {
                        __nv_bfloat162 bv = __float22bfloat162_rn(
                            make_float2(acc[mt * 7 + nt][h * 2], acc[mt * 7 + nt][h * 2 + 1]));
                        hout[(size_t)r * 32 + (c0 >> 1)] = *(unsigned*)&bv;
                    }
                }
            }
        }
    }
}

// ---------------- Aggregation 1 + fused lin2 (1 node per QUARTER-warp) -------
// 8 lanes per node; lane covers cols [8*l8, 8*l8+8) as one uint4 (8 bf16).
// Per 4-edge iteration one instruction stream serves 4 nodes: LDG issues per
// edge halved again vs half-warp, gather MLP per warp doubled again.
// lin2: smem transpose; lane jo (0..6) of each node computes output jo over
// all 64 cols (broadcast within 8-lane group; 4 distinct rows/warp at stride
// 68 -> conflict-free). No shuffles.
__global__ __launch_bounds__(256) void agg1_kernel(const float* __restrict__ b1,
                                                   const float* __restrict__ w2) {
    __shared__ float w2s[64 * OUTD];   // zero-extended rows 50..63
    __shared__ float o1s[32][68];      // row stride 68 -> bank-conflict-free
    int t = threadIdx.x;
    int hw = t >> 3;        // node slot 0..31
    int l8 = t & 7;
    for (int i = t; i < 64 * OUTD; i += 256)
        w2s[i] = (i < HID * OUTD) ? __ldg(&w2[i]) : 0.f;
    __syncthreads();
    int v = blockIdx.x * 32 + hw;   // grid 3125 * 32 = 100000 exactly
    int s0 = __ldg(&g_rowptr[v]);
    int s1 = __ldg(&g_rowptr[v + 1]);
    float dv = __ldg(&g_dinv[v]);
    const uint4* hb = (const uint4*)g_h1b;   // 8 uint4 per row

    float a[8] = {0.f, 0.f, 0.f, 0.f, 0.f, 0.f, 0.f, 0.f};
    uint4 su = __ldg(&hb[(size_t)v * 8 + l8]);
    acc_bf16x8(a, su, dv);

    int j = s0;
    for (; j + 3 < s1; j += 4) {
        int2 e0 = __ldg(&g_edge[j]);
        int2 e1 = __ldg(&g_edge[j + 1]);
        int2 e2 = __ldg(&g_edge[j + 2]);
        int2 e3 = __ldg(&g_edge[j + 3]);
        uint4 u0 = __ldg(&hb[(size_t)e0.x * 8 + l8]);
        uint4 u1 = __ldg(&hb[(size_t)e1.x * 8 + l8]);
        uint4 u2 = __ldg(&hb[(size_t)e2.x * 8 + l8]);
        uint4 u3 = __ldg(&hb[(size_t)e3.x * 8 + l8]);
        acc_bf16x8(a, u0, __int_as_float(e0.y));
        acc_bf16x8(a, u1, __int_as_float(e1.y));
        acc_bf16x8(a, u2, __int_as_float(e2.y));
        acc_bf16x8(a, u3, __int_as_float(e3.y));
    }
    for (; j < s1; j++) {
        int2 e = __ldg(&g_edge[j]);
        uint4 u = __ldg(&hb[(size_t)e.x * 8 + l8]);
        acc_bf16x8(a, u, __int_as_float(e.y));
    }

    // relu + b1 for the 8 covered cols; pad cols (f >= HID) forced to 0
    float o[8];
#pragma unroll
    for (int c = 0; c < 8; c++) {
        int f = 8 * l8 + c;
        o[c] = (f < HID) ? fmaxf(fmaf(dv, a[c], __ldg(&b1[f])), 0.f) : 0.f;
    }
    *(float4*)&o1s[hw][8 * l8]     = make_float4(o[0], o[1], o[2], o[3]);
    *(float4*)&o1s[hw][8 * l8 + 4] = make_float4(o[4], o[5], o[6], o[7]);
    __syncwarp();

    // reduction: lane jo (=l8) computes output jo over all 64 columns
    if (l8 < 7) {
        float p = 0.f;
#pragma unroll
        for (int f = 0; f < 64; f++)
            p = fmaf(o1s[hw][f], w2s[f * OUTD + l8], p);
        g_z[(size_t)v * 8 + l8] = p;
    }
}

// ---------------- Aggregation 2 (+b2, sigmoid; R6 champion form) -------------
__global__ __launch_bounds__(256) void agg2_kernel(const float* __restrict__ b2,
                                                   float* __restrict__ out) {
    int t = threadIdx.x;
    int jj = t & 7;
    int v = blockIdx.x * 32 + (t >> 3);
    int s0 = __ldg(&g_rowptr[v]);
    int s1 = __ldg(&g_rowptr[v + 1]);
    float dv = __ldg(&g_dinv[v]);
    float acc = dv * __ldg(&g_z[(size_t)v * 8 + jj]);
    int j = s0;
    for (; j + 3 < s1; j += 4) {
        int2 e0 = __ldg(&g_edge[j]);
        int2 e1 = __ldg(&g_edge[j + 1]);
        int2 e2 = __ldg(&g_edge[j + 2]);
        int2 e3 = __ldg(&g_edge[j + 3]);
        acc = fmaf(__int_as_float(e0.y), __ldg(&g_z[(size_t)e0.x * 8 + jj]), acc);
        acc = fmaf(__int_as_float(e1.y), __ldg(&g_z[(size_t)e1.x * 8 + jj]), acc);
        acc = fmaf(__int_as_float(e2.y), __ldg(&g_z[(size_t)e2.x * 8 + jj]), acc);
        acc = fmaf(__int_as_float(e3.y), __ldg(&g_z[(size_t)e3.x * 8 + jj]), acc);
    }
    for (; j < s1; j++) {
        int2 e = __ldg(&g_edge[j]);
        acc = fmaf(__int_as_float(e.y), __ldg(&g_z[(size_t)e.x * 8 + jj]), acc);
    }
    if (jj < OUTD) {
        float zz = fmaf(dv, acc, __ldg(&b2[jj]));
        out[v * OUTD + jj] = 1.f / (1.f + __expf(-zz));
    }
}

// ---------------- launch (two-stream fork/join for CSR || GEMM overlap) ------
struct AsyncRes {
    cudaStream_t s1;
    cudaEvent_t eFork, eJoin;
    AsyncRes() {
        cudaStreamCreateWithFlags(&s1, cudaStreamNonBlocking);
        cudaEventCreateWithFlags(&eFork, cudaEventDisableTiming);
        cudaEventCreateWithFlags(&eJoin, cudaEventDisableTiming);
    }
};

extern "C" void kernel_launch(void* const* d_in, const int* in_sizes, int n_in,
                              void* d_out, int out_size) {
    static AsyncRes ar;  // created on first (non-captured) correctness call

    const float* x  = (const float*)d_in[0];
    const int*   ei = (const int*)d_in[1];
    const float* w1 = (const float*)d_in[2];
    const float* b1 = (const float*)d_in[3];
    const float* w2 = (const float*)d_in[4];
    const float* b2 = (const float*)d_in[5];
    float* out = (float*)d_out;

    const int* row = ei;            // edge_index[0] = src
    const int* col = ei + NEDGES;   // edge_index[1] = dst

    // fork: CSR chain on s1, GEMM path on stream 0 — fully independent
    cudaEventRecord(ar.eFork, 0);
    cudaStreamWaitEvent(ar.s1, ar.eFork, 0);

    // stream 0: dense path
    w1pad_kernel<<<360, 256>>>(w1);
    gemm1_kernel<<<782, 128>>>(x);

    // stream s1: CSR build (hidden under gemm1)
    count_kernel<<<6250, 256, 0, ar.s1>>>(col);
    scan_local_kernel<<<98, 1024, 0, ar.s1>>>();      // also computes dinv
    scan_bsums_kernel<<<1, 128, 0, ar.s1>>>();
    scan_add_kernel<<<391, 256, 0, ar.s1>>>();        // also zeroes counts
    scatter_kernel<<<6250, 256, 0, ar.s1>>>(row, col);

    // join
    cudaEventRecord(ar.eJoin, ar.s1);
    cudaStreamWaitEvent(0, ar.eJoin, 0);

    // aggregations (need both paths)
    agg1_kernel<<<3125, 256>>>(b1, w2);               // fused lin2, 32 nodes/block
    agg2_kernel<<<3125, 256>>>(b2, out);
}